// round 17
// baseline (speedup 1.0000x reference)
#include <cuda_runtime.h>
#include <cuda_fp16.h>
#include <math.h>
#include <stdint.h>

#define NB 8192      // tokens
#define NF 2048      // feature dim (K of GEMM1)
#define NH 8192      // hidden dim  (N of GEMM1, K of GEMM2)
#define NO 2048      // out dim     (N of GEMM2)
#define NE 8
#define NSLOTS (NB * 2)

// ===================== scratch (device globals, no allocation) ==============
__device__ int   g_counts[NE];
__device__ int   g_offsets[NE];
__device__ int   g_cursor[NE];
__device__ int   g_topi[NB * 2];
__device__ float g_topw[NB * 2];
__device__ int   g_rows[NSLOTS];
__device__ int   g_slotof[NB * 2];

__device__ __align__(256) __half g_featH[(size_t)NB * NF];     // fp16 features
__device__ __align__(256) __half g_W1t[(size_t)NE * NH * NF];  // [E][N=NH][K=NF]
__device__ __align__(256) __half g_W2t[(size_t)NE * NO * NH];  // [E][N=NO][K=NH]
__device__ __align__(256) __half g_Hh[(size_t)NSLOTS * NH];    // hidden fp16
__device__ __align__(256) float  g_Y[(size_t)NSLOTS * NO];

// ===================== mma helper ===========================================
#define MMA16816(d, a, b) \
    asm volatile("mma.sync.aligned.m16n8k16.row.col.f32.f16.f16.f32 " \
        "{%0,%1,%2,%3}, {%4,%5,%6,%7}, {%8,%9}, {%0,%1,%2,%3};" \
        : "+f"((d)[0]), "+f"((d)[1]), "+f"((d)[2]), "+f"((d)[3]) \
        : "r"((a)[0]), "r"((a)[1]), "r"((a)[2]), "r"((a)[3]), \
          "r"((b)[0]), "r"((b)[1]))

// ===================== control kernels ======================================
__global__ void init_kernel() {
    int i = threadIdx.x;
    if (i < NE) g_counts[i] = 0;
}

__global__ void prefix_kernel() {
    int off = 0;
    for (int e = 0; e < NE; e++) {
        g_offsets[e] = off;
        g_cursor[e]  = off;
        off += g_counts[e];
    }
}

__global__ void router_kernel(const float* __restrict__ feat,
                              const float* __restrict__ gW,
                              const float* __restrict__ gb,
                              const float* __restrict__ eb) {
    int warp = threadIdx.x >> 5;
    int lane = threadIdx.x & 31;
    int t = blockIdx.x * 8 + warp;
    if (t >= NB) return;
    const float* fr = feat + (size_t)t * NF;
    float acc[NE];
#pragma unroll
    for (int e = 0; e < NE; e++) acc[e] = 0.f;
    for (int k = lane; k < NF; k += 32) {
        float f = fr[k];
        const float* g = gW + (size_t)k * NE;
#pragma unroll
        for (int e = 0; e < NE; e++) acc[e] = fmaf(f, g[e], acc[e]);
    }
#pragma unroll
    for (int off = 16; off > 0; off >>= 1)
#pragma unroll
        for (int e = 0; e < NE; e++)
            acc[e] += __shfl_down_sync(0xffffffffu, acc[e], off);
    if (lane == 0) {
        float best0 = -INFINITY, best1 = -INFINITY;
        int i0 = 0, i1 = 0;
#pragma unroll
        for (int e = 0; e < NE; e++) {
            float v = acc[e] + gb[e] + eb[e];
            if (v > best0) { best1 = best0; i1 = i0; best0 = v; i0 = e; }
            else if (v > best1) { best1 = v; i1 = e; }
        }
        float ew = expf(best1 - best0);
        float denom = 1.f + ew;
        g_topi[2 * t]     = i0;
        g_topi[2 * t + 1] = i1;
        g_topw[2 * t]     = 1.f / denom;
        g_topw[2 * t + 1] = ew / denom;
        atomicAdd(&g_counts[i0], 1);
        atomicAdd(&g_counts[i1], 1);
    }
}

__global__ void scatter_kernel() {
    int t = blockIdx.x * blockDim.x + threadIdx.x;
    if (t >= NB) return;
#pragma unroll
    for (int j = 0; j < 2; j++) {
        int e = g_topi[2 * t + j];
        int pos = atomicAdd(&g_cursor[e], 1);
        g_rows[pos] = t;
        g_slotof[2 * t + j] = pos;
    }
}

// ===================== conversion pre-passes ================================
__global__ void conv_feat_kernel(const float* __restrict__ f) {
    size_t i = (size_t)blockIdx.x * blockDim.x + threadIdx.x;  // over NB*NF/2
    const float2 v = ((const float2*)f)[i];
    *(__half2*)&g_featH[2 * i] = __floats2half2_rn(v.x, v.y);
}

// src [E][Kd][Nd] fp32 -> dst [E][Nd][Kd] fp16 (smem tile transpose)
__global__ void transpose_h_kernel(const float* __restrict__ src,
                                   __half* __restrict__ dst,
                                   int Kd, int Nd) {
    __shared__ float tile[64][33];
    const int e = blockIdx.z;
    const int n0 = blockIdx.x * 32;
    const int k0 = blockIdx.y * 64;
    const int tx = threadIdx.x, ty = threadIdx.y;  // (32, 8)
    const float* s = src + (size_t)e * Kd * Nd;
#pragma unroll
    for (int j = 0; j < 8; j++) {
        int k = ty + j * 8;
        tile[k][tx] = s[(size_t)(k0 + k) * Nd + n0 + tx];
    }
    __syncthreads();
#pragma unroll
    for (int j = 0; j < 4; j++) {
        int nl = ty + j * 8;
        float v0 = tile[2 * tx][nl];
        float v1 = tile[2 * tx + 1][nl];
        size_t o = ((size_t)e * Nd + n0 + nl) * Kd + k0 + 2 * tx;
        *(__half2*)(dst + o) = __floats2half2_rn(v0, v1);
    }
}

// ===================== HMMA grouped GEMM (pipelined, fp16 both sides) =======
// CTA tile 128x128, BK=32, double-buffered smem with register staging:
//   ldg(next) -> compute(cur, smem) -> sts(next, other buf) -> one sync.
// A: fp16 gathered rows (G1: g_featH via g_rows, G2: g_Hh slots).
// B: fp16 pre-transposed weights [E][N][K] -> row loader identical to A.
// 8 warps 2x4, warp tile 64x32, mma.sync.m16n8k16 f32 accum. RS=40 pad.

#define RS 40   // halves per smem row
#define RSW 20  // words per smem row

template <int K, int NN, bool G1>
__global__ __launch_bounds__(256, 2)
void moe_gemm_hmma(const __half* __restrict__ Wt,    // [E][NN][K] fp16
                   const float* __restrict__ bias) { // [E][NN]
    __shared__ __half As[2][128 * RS];
    __shared__ __half Bs[2][128 * RS];
    __shared__ int rows_s[128];

    const int e = blockIdx.z;
    const int count = g_counts[e];
    const int m0 = blockIdx.y * 128;
    if (m0 >= count) return;
    const int base = g_offsets[e];
    const int n0 = blockIdx.x * 128;
    const int tid = threadIdx.x;

    if (tid < 128) {
        int m = m0 + tid;
        if (m > count - 1) m = count - 1;
        rows_s[tid] = G1 ? g_rows[base + m] : (base + m);
    }
    __syncthreads();

    // loader indices: each thread owns one 16-half (32B) segment of one row
    const int ra = tid >> 1;             // row 0..127 (A: M-row, B: N-row)
    const int kq = (tid & 1) * 16;       // k-offset 0/16

    const __half* Ag = G1 ? g_featH : g_Hh;
    const __half* ap0 = Ag + (size_t)rows_s[ra] * K + kq;
    const __half* bq0 = Wt + ((size_t)e * NN + n0 + ra) * K + kq;

    const int w = tid >> 5, lane = tid & 31;
    const int wm = w & 1, wn = w >> 1;   // 2 x 4 warps
    const int lq = lane >> 2, lr = lane & 3;

    float acc[4][4][4];
#pragma unroll
    for (int a = 0; a < 4; a++)
#pragma unroll
        for (int b = 0; b < 4; b++)
#pragma unroll
            for (int c = 0; c < 4; c++) acc[a][b][c] = 0.f;

    // register staging: A and B 16 halves each
    uint4 sa0, sa1, sb0, sb1;

    auto ldg = [&](int k0) {
        const __half* ap = ap0 + k0;
        sa0 = ((const uint4*)ap)[0];
        sa1 = ((const uint4*)ap)[1];
        const __half* bp = bq0 + k0;
        sb0 = ((const uint4*)bp)[0];
        sb1 = ((const uint4*)bp)[1];
    };
    auto sts = [&](int buf) {
        __half* da = &As[buf][ra * RS + kq];
        ((uint4*)da)[0] = sa0;
        ((uint4*)da)[1] = sa1;
        __half* db = &Bs[buf][ra * RS + kq];
        ((uint4*)db)[0] = sb0;
        ((uint4*)db)[1] = sb1;
    };

    constexpr int NCH = K / 32;
    ldg(0);
    sts(0);
    __syncthreads();

    for (int i = 0; i < NCH; i++) {
        if (i + 1 < NCH) ldg((i + 1) * 32);

        const uint32_t* As32 = (const uint32_t*)As[i & 1];
        const uint32_t* Bs32 = (const uint32_t*)Bs[i & 1];
#pragma unroll
        for (int ks = 0; ks < 2; ks++) {
            const int cc = ks * 8 + lr;
            uint32_t af[4][4], bf[4][2];
#pragma unroll
            for (int mt = 0; mt < 4; mt++) {
                int r0 = wm * 64 + mt * 16 + lq;
                af[mt][0] = As32[r0 * RSW + cc];
                af[mt][1] = As32[(r0 + 8) * RSW + cc];
                af[mt][2] = As32[r0 * RSW + cc + 4];
                af[mt][3] = As32[(r0 + 8) * RSW + cc + 4];
            }
#pragma unroll
            for (int nt = 0; nt < 4; nt++) {
                int nr = wn * 32 + nt * 8 + lq;
                bf[nt][0] = Bs32[nr * RSW + cc];
                bf[nt][1] = Bs32[nr * RSW + cc + 4];
            }
#pragma unroll
            for (int mt = 0; mt < 4; mt++)
#pragma unroll
                for (int nt = 0; nt < 4; nt++)
                    MMA16816(acc[mt][nt], af[mt], bf[nt]);
        }

        if (i + 1 < NCH) sts((i + 1) & 1);
        __syncthreads();
    }

    // ---- epilogue ----
    const float* bpb = bias + (size_t)e * NN + n0;
#pragma unroll
    for (int mt = 0; mt < 4; mt++) {
#pragma unroll
        for (int hh = 0; hh < 2; hh++) {
            int m = m0 + wm * 64 + mt * 16 + lq + hh * 8;
            if (m < count) {
                size_t orow = (size_t)(base + m) * NN + n0;
#pragma unroll
                for (int nt = 0; nt < 4; nt++) {
                    int col = wn * 32 + nt * 8 + lr * 2;
                    float x0 = acc[mt][nt][hh * 2 + 0] + bpb[col];
                    float x1 = acc[mt][nt][hh * 2 + 1] + bpb[col + 1];
                    if (G1) {
                        x0 = fmaxf(x0, 0.f);
                        x1 = fmaxf(x1, 0.f);
                        *(__half2*)&g_Hh[orow + col] = __floats2half2_rn(x0, x1);
                    } else {
                        *(float2*)&g_Y[orow + col] = make_float2(x0, x1);
                    }
                }
            }
        }
    }
}

// ===================== combine ==============================================
__global__ void combine_kernel(float* __restrict__ out) {
    int idx = blockIdx.x * blockDim.x + threadIdx.x;
    int t = idx / (NO / 4);
    int c = (idx % (NO / 4)) * 4;
    if (t >= NB) return;
    float w0 = g_topw[2 * t];
    float w1 = g_topw[2 * t + 1];
    int s0 = g_slotof[2 * t];
    int s1 = g_slotof[2 * t + 1];
    float4 y0 = *(const float4*)&g_Y[(size_t)s0 * NO + c];
    float4 y1 = *(const float4*)&g_Y[(size_t)s1 * NO + c];
    float4 r;
    r.x = w0 * y0.x + w1 * y1.x;
    r.y = w0 * y0.y + w1 * y1.y;
    r.z = w0 * y0.z + w1 * y1.z;
    r.w = w0 * y0.w + w1 * y1.w;
    *(float4*)&out[(size_t)t * NO + c] = r;
}

// ===================== launch ===============================================
extern "C" void kernel_launch(void* const* d_in, const int* in_sizes, int n_in,
                              void* d_out, int out_size) {
    const float* feat = (const float*)d_in[0];
    const float* gW   = (const float*)d_in[1];
    const float* gb   = (const float*)d_in[2];
    const float* eb   = (const float*)d_in[3];
    const float* W1   = (const float*)d_in[4];  // [E, NF, NH]
    const float* b1   = (const float*)d_in[5];
    const float* W2   = (const float*)d_in[6];  // [E, NH, NO]
    const float* b2   = (const float*)d_in[7];
    float* out = (float*)d_out;

    init_kernel<<<1, 32>>>();
    router_kernel<<<NB / 8, 256>>>(feat, gW, gb, eb);
    prefix_kernel<<<1, 1>>>();
    scatter_kernel<<<NB / 256, 256>>>();
    conv_feat_kernel<<<(NB * NF / 2) / 256, 256>>>(feat);
    {
        dim3 g1(NH / 32, NF / 64, NE);
        transpose_h_kernel<<<g1, dim3(32, 8)>>>(W1, g_W1t, NF, NH);
        dim3 g2(NO / 32, NH / 64, NE);
        transpose_h_kernel<<<g2, dim3(32, 8)>>>(W2, g_W2t, NH, NO);
    }

    {
        dim3 grid(NH / 128, NB / 128, NE);
        moe_gemm_hmma<NF, NH, true><<<grid, 256>>>(g_W1t, b1);
    }
    {
        dim3 grid(NO / 128, NB / 128, NE);
        moe_gemm_hmma<NH, NO, false><<<grid, 256>>>(g_W2t, b2);
    }
    combine_kernel<<<(NB * NO / 4) / 256, 256>>>(out);
}